// round 1
// baseline (speedup 1.0000x reference)
#include <cuda_runtime.h>
#include <math.h>

#define HIDDEN 150
#define EMBED 300
#define OUTC 5
#define DEPTH 13
#define NN 8191          // 2^13 - 1
#define LL 4096          // leaves
#define LEAF_START 4095  // 2^12 - 1

// ---------------- device scratch (no allocs allowed) ----------------
__device__ float g_H[NN * HIDDEN];
__device__ float g_C[NN * HIDDEN];
__device__ float g_G[LL * 450];          // pre-activation scratch (max of 4096*450, 2048*750)
__device__ float g_WL[450 * EMBED];      // stacked [Wi; Wo; Wu]
__device__ float g_WU[750 * EMBED];      // stacked [U0i|U1i; U00f|U01f; U10f|U11f; U0o|U1o; U0u|U1u]
__device__ float g_bL[450];
__device__ float g_bU[750];

__device__ __forceinline__ float sigmoidf(float x) {
    return 1.0f / (1.0f + expf(-x));
}

// ---------------- weight stacking ----------------
__global__ void prep_kernel(
    const float* __restrict__ Wi, const float* __restrict__ bi,
    const float* __restrict__ Wo, const float* __restrict__ bo,
    const float* __restrict__ Wu, const float* __restrict__ bu,
    const float* __restrict__ U0i, const float* __restrict__ U1i, const float* __restrict__ bbi,
    const float* __restrict__ U00f, const float* __restrict__ U01f,
    const float* __restrict__ U10f, const float* __restrict__ U11f, const float* __restrict__ bbf,
    const float* __restrict__ U0o, const float* __restrict__ U1o, const float* __restrict__ bbo,
    const float* __restrict__ U0u, const float* __restrict__ U1u, const float* __restrict__ bbu)
{
    int t = blockIdx.x * blockDim.x + threadIdx.x;
    int stride = gridDim.x * blockDim.x;

    for (int i = t; i < 450 * EMBED; i += stride) {
        int n = i / EMBED, k = i % EMBED;
        float v;
        if (n < 150)       v = Wi[n * EMBED + k];
        else if (n < 300)  v = Wo[(n - 150) * EMBED + k];
        else               v = Wu[(n - 300) * EMBED + k];
        g_WL[i] = v;
    }
    for (int i = t; i < 750 * EMBED; i += stride) {
        int n = i / EMBED, k = i % EMBED;
        int gate = n / 150, r = n % 150;
        const float* U0; const float* U1;
        switch (gate) {
            case 0:  U0 = U0i;  U1 = U1i;  break;
            case 1:  U0 = U00f; U1 = U01f; break;
            case 2:  U0 = U10f; U1 = U11f; break;
            case 3:  U0 = U0o;  U1 = U1o;  break;
            default: U0 = U0u;  U1 = U1u;  break;
        }
        g_WU[i] = (k < 150) ? U0[r * 150 + k] : U1[r * 150 + (k - 150)];
    }
    if (t < 450) {
        int gate = t / 150, r = t % 150;
        g_bL[t] = (gate == 0) ? bi[r] : (gate == 1) ? bo[r] : bu[r];
    }
    if (t < 750) {
        int gate = t / 150, r = t % 150;
        g_bU[t] = (gate == 0) ? bbi[r]
                : (gate <= 2) ? bbf[r]
                : (gate == 3) ? bbo[r] : bbu[r];
    }
}

// ---------------- SGEMM: G[m][n] = sum_k A[m][k] * W[n][k] ----------------
// mode 0: leaf  — A row m = word_embedding[words[LEAF_START+m]], W = g_WL, N = 450
// mode 1: inner — A = g_H + (2s+1)*HIDDEN, lda = 300 (children are contiguous), W = g_WU, N = 750
#define BM 64
#define BN 64
#define BK 20   // 300 = 15 * 20

__global__ __launch_bounds__(256)
void gemm_kernel(int mode, int s, int M, int N,
                 const float* __restrict__ emb,
                 const int* __restrict__ words)
{
    __shared__ float As[BK][BM];
    __shared__ float Ws[BK][BN];
    __shared__ long  rowOff[BM];

    const float* W     = (mode == 0) ? g_WL : g_WU;
    const float* Abase = (mode == 0) ? emb : (g_H + (long)(2 * s + 1) * HIDDEN);

    int bm = blockIdx.x * BM;
    int bn = blockIdx.y * BN;
    int tid = threadIdx.x;         // 256 threads
    int tx = tid % 16, ty = tid / 16;

    if (tid < BM) {
        int m = bm + tid;
        long off = -1;
        if (m < M) {
            if (mode == 0) off = (long)words[LEAF_START + m] * EMBED;
            else           off = (long)m * EMBED;
        }
        rowOff[tid] = off;
    }
    __syncthreads();

    float acc[4][4] = {};

    for (int k0 = 0; k0 < EMBED; k0 += BK) {
        // A tile: 64 x 20 = 1280 elems, 5 per thread
        #pragma unroll
        for (int l = 0; l < 5; l++) {
            int e  = tid + l * 256;
            int ml = e / BK, kk = e % BK;
            long off = rowOff[ml];
            As[kk][ml] = (off >= 0) ? Abase[off + k0 + kk] : 0.0f;
        }
        // W tile: 64 x 20
        #pragma unroll
        for (int l = 0; l < 5; l++) {
            int e  = tid + l * 256;
            int nl = e / BK, kk = e % BK;
            int n  = bn + nl;
            Ws[kk][nl] = (n < N) ? W[(long)n * EMBED + k0 + kk] : 0.0f;
        }
        __syncthreads();

        #pragma unroll
        for (int kk = 0; kk < BK; kk++) {
            float a[4], b[4];
            #pragma unroll
            for (int i = 0; i < 4; i++) a[i] = As[kk][ty * 4 + i];
            #pragma unroll
            for (int j = 0; j < 4; j++) b[j] = Ws[kk][tx * 4 + j];
            #pragma unroll
            for (int i = 0; i < 4; i++)
                #pragma unroll
                for (int j = 0; j < 4; j++)
                    acc[i][j] += a[i] * b[j];
        }
        __syncthreads();
    }

    #pragma unroll
    for (int i = 0; i < 4; i++) {
        int m = bm + ty * 4 + i;
        if (m >= M) continue;
        #pragma unroll
        for (int j = 0; j < 4; j++) {
            int n = bn + tx * 4 + j;
            if (n < N) g_G[(long)m * N + n] = acc[i][j];
        }
    }
}

// ---------------- leaf activation ----------------
__global__ void leaf_act()
{
    int i = blockIdx.x * blockDim.x + threadIdx.x;
    if (i >= LL * HIDDEN) return;
    int m = i / HIDDEN, j = i % HIDDEN;
    const float* g = g_G + (long)m * 450;
    float ig = sigmoidf(g[j]       + g_bL[j]);
    float og = sigmoidf(g[150 + j] + g_bL[150 + j]);
    float uv = tanhf   (g[300 + j] + g_bL[300 + j]);
    float c = ig * uv;
    float h = og * tanhf(c);
    int node = LEAF_START + m;
    g_H[(long)node * HIDDEN + j] = h;
    g_C[(long)node * HIDDEN + j] = c;
}

// ---------------- internal-node activation ----------------
__global__ void inner_act(int s, int M)
{
    int i = blockIdx.x * blockDim.x + threadIdx.x;
    if (i >= M * HIDDEN) return;
    int m = i / HIDDEN, j = i % HIDDEN;
    const float* g = g_G + (long)m * 750;
    float ig = sigmoidf(g[j]       + g_bU[j]);
    float fl = sigmoidf(g[150 + j] + g_bU[150 + j]);
    float fr = sigmoidf(g[300 + j] + g_bU[300 + j]);
    float og = sigmoidf(g[450 + j] + g_bU[450 + j]);
    float uv = tanhf   (g[600 + j] + g_bU[600 + j]);
    int node = s + m;
    float lc = g_C[(long)(2 * node + 1) * HIDDEN + j];
    float rc = g_C[(long)(2 * node + 2) * HIDDEN + j];
    float c = ig * uv + fl * lc + fr * rc;
    float h = og * tanhf(c);
    g_H[(long)node * HIDDEN + j] = h;
    g_C[(long)node * HIDDEN + j] = c;
}

// ---------------- loss ----------------
__global__ void zero_out(float* out)
{
    if (threadIdx.x == 0 && blockIdx.x == 0) out[0] = 0.0f;
}

__global__ void loss_kernel(const float* __restrict__ Why,
                            const float* __restrict__ by,
                            const int*   __restrict__ scores,
                            float* __restrict__ out)
{
    int gw   = (blockIdx.x * blockDim.x + threadIdx.x) >> 5;
    int lane = threadIdx.x & 31;
    if (gw >= NN) return;

    const float* h = g_H + (long)gw * HIDDEN;
    float logits[OUTC];
    #pragma unroll
    for (int o = 0; o < OUTC; o++) {
        float sacc = 0.0f;
        for (int k = lane; k < HIDDEN; k += 32)
            sacc += Why[o * HIDDEN + k] * h[k];
        #pragma unroll
        for (int d = 16; d > 0; d >>= 1)
            sacc += __shfl_xor_sync(0xffffffff, sacc, d);
        logits[o] = sacc + by[o];
    }
    if (lane == 0) {
        float mx = logits[0];
        #pragma unroll
        for (int o = 1; o < OUTC; o++) mx = fmaxf(mx, logits[o]);
        float se = 0.0f;
        #pragma unroll
        for (int o = 0; o < OUTC; o++) se += expf(logits[o] - mx);
        float lse = mx + logf(se);
        int sc = scores[gw];
        atomicAdd(out, lse - logits[sc]);
    }
}

// ---------------- launch ----------------
extern "C" void kernel_launch(void* const* d_in, const int* in_sizes, int n_in,
                              void* d_out, int out_size)
{
    const float* Wi   = (const float*)d_in[0];
    const float* bi   = (const float*)d_in[1];
    const float* Wo   = (const float*)d_in[2];
    const float* bo   = (const float*)d_in[3];
    const float* Wu   = (const float*)d_in[4];
    const float* bu   = (const float*)d_in[5];
    const float* U0i  = (const float*)d_in[6];
    const float* U1i  = (const float*)d_in[7];
    const float* bbi  = (const float*)d_in[8];
    const float* U00f = (const float*)d_in[9];
    const float* U01f = (const float*)d_in[10];
    const float* U10f = (const float*)d_in[11];
    const float* U11f = (const float*)d_in[12];
    const float* bbf  = (const float*)d_in[13];
    const float* U0o  = (const float*)d_in[14];
    const float* U1o  = (const float*)d_in[15];
    const float* bbo  = (const float*)d_in[16];
    const float* U0u  = (const float*)d_in[17];
    const float* U1u  = (const float*)d_in[18];
    const float* bbu  = (const float*)d_in[19];
    const float* Why  = (const float*)d_in[20];
    const float* by   = (const float*)d_in[21];
    const float* emb  = (const float*)d_in[22];
    const int*   scores = (const int*)d_in[23];
    const int*   words  = (const int*)d_in[24];
    // d_in[25] = lchs, d_in[26] = rchs — implicit in the perfect-tree layout

    float* out = (float*)d_out;

    zero_out<<<1, 32>>>(out);
    prep_kernel<<<240, 256>>>(Wi, bi, Wo, bo, Wu, bu,
                              U0i, U1i, bbi,
                              U00f, U01f, U10f, U11f, bbf,
                              U0o, U1o, bbo,
                              U0u, U1u, bbu);

    // leaf level: M=4096, N=450, K=300 (gathered embedding rows)
    {
        dim3 grid((LL + BM - 1) / BM, (450 + BN - 1) / BN);
        gemm_kernel<<<grid, 256>>>(0, 0, LL, 450, emb, words);
        int tot = LL * HIDDEN;
        leaf_act<<<(tot + 255) / 256, 256>>>();
    }

    // internal levels, bottom-up
    for (int d = DEPTH - 2; d >= 0; d--) {
        int s = (1 << d) - 1;
        int M = 1 << d;
        dim3 grid((M + BM - 1) / BM, (750 + BN - 1) / BN);
        gemm_kernel<<<grid, 256>>>(1, s, M, 750, nullptr, nullptr);
        int tot = M * HIDDEN;
        inner_act<<<(tot + 255) / 256, 256>>>(s, M);
    }

    // final loss over all 8191 nodes
    {
        int threads = 256;
        int warpsPerBlock = threads / 32;
        int blocks = (NN + warpsPerBlock - 1) / warpsPerBlock;
        loss_kernel<<<blocks, threads>>>(Why, by, scores, out);
    }
    (void)in_sizes; (void)n_in; (void)out_size;
}